// round 16
// baseline (speedup 1.0000x reference)
#include <cuda_runtime.h>

// OnnxNonMaxSuppression: B=8, C=80, N=16384, max_out=50. Output float32.
//
// Round-16 vs R15 (43.3us):
//  - streaming: 2 batches of 8 back-to-back float4 loads into registers
//    (guaranteed MLP=8; no branch/atomic between loads), one 16-way fmax
//    tree + single rare branch per batch.
//  - walk: precomputed reject-bitmask matrix over the first 128 sorted
//    candidates (all 8 warps, lane-parallel ballots), then a single-thread
//    mask scan (~25 cyc/candidate). Same IoU tests, same order => same
//    picks. Beyond-128 and histogram fallback keep the direct-test path.
// Exactness unchanged: sorted-walk == greedy NMS, reference IoU rounding.

#define NMS_B      8
#define NMS_C      80
#define NMS_N      16384
#define NMS_MAXOUT 50
#define NT         256
#define NBUCKET    1024
#define CAP        256
#define TARGET     128
#define WMAT       128                             // matrix-walk window
#define IOU_THR    0.5f
#define SCORE_THR  0.5f
#define BITS_BASE  0x3F000001u                     // smallest float bits > 0.5f
#define T0_BUCKET  1011                            // top 13 buckets, E~104
#define T0_BITS    (BITS_BASE + ((unsigned)T0_BUCKET << 13))

__device__ __forceinline__ unsigned score_bucket(unsigned bits) {
    unsigned bkt = (bits - BITS_BASE) >> 13;
    return bkt > (NBUCKET - 1) ? (NBUCKET - 1) : bkt;
}

// Reference-exact IoU rejection test (no-FMA, operand order preserved).
__device__ __forceinline__ bool iou_reject(
    float px1, float py1, float px2, float py2, float pa,
    float qx1, float qy1, float qx2, float qy2, float qa)
{
    float x1 = fmaxf(px1, qx1);
    float y1 = fmaxf(py1, qy1);
    float x2 = fminf(px2, qx2);
    float y2 = fminf(py2, qy2);
    float w  = fmaxf(x2 - x1, 0.0f);
    float h  = fmaxf(y2 - y1, 0.0f);
    float inter = __fmul_rn(w, h);
    float uni   = __fsub_rn(__fadd_rn(pa, qa), inter);
    float iou   = inter / fmaxf(uni, 1e-9f);
    return iou > IOU_THR;
}

__global__ void __launch_bounds__(NT, 4) nms_kernel(
    const float* __restrict__ boxes,    // [B, N, 4]
    const float* __restrict__ scores,   // [B, C, N]
    float* __restrict__ out)            // [B*C*50, 3] float32
{
    __shared__ unsigned           hist[NBUCKET];   // fallback only
    __shared__ unsigned long long keys[CAP];
    __shared__ float cx1[CAP], cy1[CAP], cx2[CAP], cy2[CAP], car[CAP];
    __shared__ float ax1[64], ay1[64], ax2[64], ay2[64], aar[64];
    __shared__ unsigned rejm[WMAT][4];             // reject bitmask matrix
    __shared__ int   sh_cnt, sh_lo, sh_acc;

    const int lane = blockIdx.x;        // b*C + c
    const int b    = lane / NMS_C;
    const int c    = lane - b * NMS_C;
    const int tid  = threadIdx.x;
    const int wid  = tid >> 5;
    const int lid  = tid & 31;

    const float*  sc  = scores + (size_t)lane * NMS_N;
    const float4* sc4 = reinterpret_cast<const float4*>(sc);
    const float*  bx  = boxes + (size_t)b * NMS_N * 4;
    float* orow       = out + (size_t)lane * (NMS_MAXOUT * 3);

    if (tid == 0) sh_cnt = 0;
    __syncthreads();

    // ---- streaming pass: 2 batches of 8 back-to-back float4 loads ----
    const float t0f = __uint_as_float(T0_BITS);    // positive-float bit order
    #pragma unroll
    for (int k = 0; k < 2; k++) {
        float4 v[8];
        #pragma unroll
        for (int j = 0; j < 8; j++)
            v[j] = sc4[(k * 8 + j) * NT + tid];    // independent, batched
        float m01 = fmaxf(fmaxf(v[0].x, v[0].y), fmaxf(v[0].z, v[0].w));
        #pragma unroll
        for (int j = 1; j < 8; j++)
            m01 = fmaxf(m01, fmaxf(fmaxf(v[j].x, v[j].y), fmaxf(v[j].z, v[j].w)));
        if (m01 >= t0f) {                          // rare (~5% of batches)
            #pragma unroll
            for (int j = 0; j < 8; j++) {
                float vs[4] = {v[j].x, v[j].y, v[j].z, v[j].w};
                #pragma unroll
                for (int q = 0; q < 4; q++) {
                    if (vs[q] >= t0f) {
                        int pos = atomicAdd(&sh_cnt, 1);
                        if (pos < CAP) {
                            unsigned bits = __float_as_uint(vs[q]);
                            keys[pos] = ((unsigned long long)bits << 32)
                                      | (unsigned)(~(unsigned)(((k*8+j)*NT + tid)*4 + q));
                        }
                    }
                }
            }
        }
    }
    __syncthreads();

    int acc = 0;
    const int cnt     = sh_cnt;
    const bool fastOK = (cnt <= CAP);

    if (fastOK) {
        // ---- rank sort fused with box prefetch ----
        unsigned long long my = 0ULL;
        float x1 = 0, y1 = 0, x2 = 0, y2 = 0;
        if (tid < cnt) {
            my = keys[tid];
            unsigned idx = ~(unsigned)my;
            const float* p = bx + (size_t)idx * 4;
            x1 = p[0]; y1 = p[1]; x2 = p[2]; y2 = p[3];
        }
        int rank = 0;
        if (tid < cnt) {
            #pragma unroll 4
            for (int j = 0; j < cnt; j++)
                rank += (keys[j] > my);            // distinct keys -> permutation
        }
        // zero the reject matrix while ranks settle
        for (int i = tid; i < WMAT * 4; i += NT)
            ((unsigned*)rejm)[i] = 0u;
        __syncthreads();
        if (tid < cnt) {
            keys[rank] = my;
            cx1[rank] = x1; cy1[rank] = y1; cx2[rank] = x2; cy2[rank] = y2;
            car[rank] = __fmul_rn(x2 - x1, y2 - y1);
        }
        __syncthreads();

        // ---- build reject matrix: warp w handles i = w, w+8, ... ----
        const int W = (cnt < WMAT) ? cnt : WMAT;
        for (int i = wid; i < W; i += 8) {
            float qx1 = cx1[i], qy1 = cy1[i];      // broadcast LDS
            float qx2 = cx2[i], qy2 = cy2[i], qa = car[i];
            for (int cb = 0; cb * 32 < i; cb++) {
                int j = cb * 32 + lid;
                bool rej = false;
                if (j < i)
                    rej = iou_reject(cx1[j], cy1[j], cx2[j], cy2[j], car[j],
                                     qx1, qy1, qx2, qy2, qa);
                unsigned word = __ballot_sync(0xffffffffu, rej);
                if (lid == 0) rejm[i][cb] = word;
            }
        }
        __syncthreads();

        // ---- single-thread mask scan (j < W), direct test beyond ----
        if (tid == 0) {
            unsigned M0 = 0, M1 = 0, M2 = 0, M3 = 0;
            int a = 0;
            for (int j2 = 0; j2 < cnt && a < NMS_MAXOUT; j2++) {
                bool rej;
                if (j2 < W) {
                    unsigned r = (rejm[j2][0] & M0) | (rejm[j2][1] & M1)
                               | (rejm[j2][2] & M2) | (rejm[j2][3] & M3);
                    rej = (r != 0u);
                } else {
                    rej = false;
                    float qx1 = cx1[j2], qy1 = cy1[j2];
                    float qx2 = cx2[j2], qy2 = cy2[j2], qa = car[j2];
                    for (int t = 0; t < a && !rej; t++)
                        rej = iou_reject(ax1[t], ay1[t], ax2[t], ay2[t], aar[t],
                                         qx1, qy1, qx2, qy2, qa);
                }
                if (!rej) {
                    unsigned idx = ~(unsigned)keys[j2];
                    orow[a * 3 + 0] = (float)b;
                    orow[a * 3 + 1] = (float)c;
                    orow[a * 3 + 2] = (float)idx;
                    ax1[a] = cx1[j2]; ay1[a] = cy1[j2];
                    ax2[a] = cx2[j2]; ay2[a] = cy2[j2]; aar[a] = car[j2];
                    if      (j2 < 32)  M0 |= 1u << j2;
                    else if (j2 < 64)  M1 |= 1u << (j2 - 32);
                    else if (j2 < 96)  M2 |= 1u << (j2 - 64);
                    else if (j2 < 128) M3 |= 1u << (j2 - 96);
                    a++;
                }
            }
            sh_acc = a;
        }
        __syncthreads();
        acc = sh_acc;
    }

    // ---- exact fallback (block-uniform; statistically never taken) ----
    if (acc < NMS_MAXOUT) {
        for (int i = tid; i < NBUCKET; i += NT) hist[i] = 0;
        __syncthreads();
        for (int i = tid; i < NMS_N; i += NT) {
            float v = sc[i];
            if (v > SCORE_THR)
                atomicAdd(&hist[score_bucket(__float_as_uint(v))], 1u);
        }
        __syncthreads();

        int hi = fastOK ? T0_BUCKET : NBUCKET;
        while (acc < NMS_MAXOUT && hi > 0) {
            if (tid == 0) {
                unsigned cum = 0;
                int lo = hi;
                while (lo > 0) {
                    unsigned n2 = hist[lo - 1];
                    if (cum + n2 > CAP && cum > 0) break;
                    cum += n2;
                    lo--;
                    if (cum >= TARGET) break;
                }
                sh_lo  = lo;
                sh_cnt = 0;
            }
            __syncthreads();
            const int lo = sh_lo;

            for (int i = tid; i < NMS_N; i += NT) {
                float v = sc[i];
                if (v > SCORE_THR) {
                    unsigned bits = __float_as_uint(v);
                    int bkt = (int)score_bucket(bits);
                    if (bkt >= lo && bkt < hi) {
                        int pos = atomicAdd(&sh_cnt, 1);
                        if (pos < CAP)
                            keys[pos] = ((unsigned long long)bits << 32)
                                      | (unsigned)(~(unsigned)i);
                    }
                }
            }
            __syncthreads();
            const int n = (sh_cnt < CAP) ? sh_cnt : CAP;

            unsigned long long my = 0ULL;
            float x1 = 0, y1 = 0, x2 = 0, y2 = 0;
            if (tid < n) {
                my = keys[tid];
                unsigned idx = ~(unsigned)my;
                const float* p = bx + (size_t)idx * 4;
                x1 = p[0]; y1 = p[1]; x2 = p[2]; y2 = p[3];
            }
            int rank = 0;
            if (tid < n) {
                #pragma unroll 4
                for (int j = 0; j < n; j++)
                    rank += (keys[j] > my);
            }
            __syncthreads();
            if (tid < n) {
                keys[rank] = my;
                cx1[rank] = x1; cy1[rank] = y1; cx2[rank] = x2; cy2[rank] = y2;
                car[rank] = __fmul_rn(x2 - x1, y2 - y1);
            }
            __syncthreads();

            if (tid < 32) {
                const int l = tid;
                int a = acc;
                for (int j2 = 0; j2 < n && a < NMS_MAXOUT; j2++) {
                    float qx1 = cx1[j2], qy1 = cy1[j2];
                    float qx2 = cx2[j2], qy2 = cy2[j2], qa = car[j2];
                    bool rej = false;
                    if (l < a)
                        rej = iou_reject(ax1[l], ay1[l], ax2[l], ay2[l], aar[l],
                                         qx1, qy1, qx2, qy2, qa);
                    if (l + 32 < a)
                        rej |= iou_reject(ax1[l+32], ay1[l+32], ax2[l+32],
                                          ay2[l+32], aar[l+32],
                                          qx1, qy1, qx2, qy2, qa);
                    if (__ballot_sync(0xffffffffu, rej) == 0u) {
                        if (l == 0) {
                            unsigned idx = ~(unsigned)keys[j2];
                            orow[a * 3 + 0] = (float)b;
                            orow[a * 3 + 1] = (float)c;
                            orow[a * 3 + 2] = (float)idx;
                            ax1[a] = qx1; ay1[a] = qy1;
                            ax2[a] = qx2; ay2[a] = qy2; aar[a] = qa;
                        }
                        __syncwarp();
                        a++;
                    }
                }
                if (l == 0) sh_acc = a;
            }
            __syncthreads();
            acc = sh_acc;
            hi  = lo;
        }
    }

    // ---- pad remaining rows with -1 ----
    for (int j = acc * 3 + tid; j < NMS_MAXOUT * 3; j += NT)
        orow[j] = -1.0f;
}

extern "C" void kernel_launch(void* const* d_in, const int* in_sizes, int n_in,
                              void* d_out, int out_size)
{
    const float* boxes  = nullptr;   // 524288 elems
    const float* scores = nullptr;   // 10485760 elems
    for (int i = 0; i < n_in; i++) {
        int sz = in_sizes[i];
        if (sz == NMS_B * NMS_N * 4 || sz == NMS_B * NMS_N * 4 * 4)
            boxes = (const float*)d_in[i];
        else if (sz == NMS_B * NMS_C * NMS_N || sz == NMS_B * NMS_C * NMS_N * 4)
            scores = (const float*)d_in[i];
    }
    if (boxes  == nullptr) boxes  = (const float*)d_in[0];
    if (scores == nullptr) scores = (const float*)d_in[1];

    nms_kernel<<<NMS_B * NMS_C, NT>>>(boxes, scores, (float*)d_out);
}

// round 17
// speedup vs baseline: 1.2001x; 1.2001x over previous
#include <cuda_runtime.h>

// OnnxNonMaxSuppression: B=8, C=80, N=16384, max_out=50. Output float32.
//
// Round-17: R15 (best, 43.3us) byte-identical except __launch_bounds__
// (256,4) -> (256,6). Empirical law from R12-R16: streaming HBM BW scales
// with resident warps (~28 GB/s/warp, latency-capped); R16 showed buying
// per-warp MLP with registers costs occupancy and loses. So buy warps:
// 42-reg cap -> 6 blocks/SM -> 48 warps (75% occ) vs 33.
// Exactness unchanged: sorted-walk == greedy NMS, reference IoU rounding,
// histogram-chunk fallback for overflow/shortfall.

#define NMS_B      8
#define NMS_C      80
#define NMS_N      16384
#define NMS_MAXOUT 50
#define NT         256
#define NBUCKET    1024
#define CAP        256
#define TARGET     128
#define IOU_THR    0.5f
#define SCORE_THR  0.5f
#define BITS_BASE  0x3F000001u                     // smallest float bits > 0.5f
#define T0_BUCKET  1011                            // top 13 buckets, E~104
#define T0_BITS    (BITS_BASE + ((unsigned)T0_BUCKET << 13))

__device__ __forceinline__ unsigned score_bucket(unsigned bits) {
    unsigned bkt = (bits - BITS_BASE) >> 13;
    return bkt > (NBUCKET - 1) ? (NBUCKET - 1) : bkt;
}

// Reference-exact IoU rejection test (no-FMA, operand order preserved).
__device__ __forceinline__ bool iou_reject(
    float px1, float py1, float px2, float py2, float pa,
    float qx1, float qy1, float qx2, float qy2, float qa)
{
    float x1 = fmaxf(px1, qx1);
    float y1 = fmaxf(py1, qy1);
    float x2 = fminf(px2, qx2);
    float y2 = fminf(py2, qy2);
    float w  = fmaxf(x2 - x1, 0.0f);
    float h  = fmaxf(y2 - y1, 0.0f);
    float inter = __fmul_rn(w, h);
    float uni   = __fsub_rn(__fadd_rn(pa, qa), inter);
    float iou   = inter / fmaxf(uni, 1e-9f);
    return iou > IOU_THR;
}

__global__ void __launch_bounds__(NT, 6) nms_kernel(
    const float* __restrict__ boxes,    // [B, N, 4]
    const float* __restrict__ scores,   // [B, C, N]
    float* __restrict__ out)            // [B*C*50, 3] float32
{
    __shared__ unsigned           hist[NBUCKET];   // fallback only
    __shared__ unsigned long long keys[CAP];
    __shared__ float cx1[CAP], cy1[CAP], cx2[CAP], cy2[CAP], car[CAP];
    __shared__ float ax1[64], ay1[64], ax2[64], ay2[64], aar[64];
    __shared__ int   sh_cnt, sh_lo, sh_acc;

    const int lane = blockIdx.x;        // b*C + c
    const int b    = lane / NMS_C;
    const int c    = lane - b * NMS_C;
    const int tid  = threadIdx.x;

    const float*  sc  = scores + (size_t)lane * NMS_N;
    const float4* sc4 = reinterpret_cast<const float4*>(sc);
    const float*  bx  = boxes + (size_t)b * NMS_N * 4;
    float* orow       = out + (size_t)lane * (NMS_MAXOUT * 3);

    if (tid == 0) sh_cnt = 0;
    __syncthreads();

    // ---- streaming pass: collect top-chunk keys (unsorted) ----
    const float t0f = __uint_as_float(T0_BITS);    // positive-float bit order
    #pragma unroll
    for (int k = 0; k < NMS_N / (4 * NT); k++) {   // 16 float4 per thread
        int    i4 = k * NT + tid;
        float4 v4 = sc4[i4];
        // fast reject: does ANY of the 4 reach the threshold?
        float m = fmaxf(fmaxf(v4.x, v4.y), fmaxf(v4.z, v4.w));
        if (m >= t0f) {                            // rare (~2.5% of float4s)
            float vs[4] = {v4.x, v4.y, v4.z, v4.w};
            #pragma unroll
            for (int q = 0; q < 4; q++) {
                if (vs[q] >= t0f) {                // == bits >= T0_BITS
                    int pos = atomicAdd(&sh_cnt, 1);
                    if (pos < CAP) {
                        unsigned bits = __float_as_uint(vs[q]);
                        keys[pos] = ((unsigned long long)bits << 32)
                                  | (unsigned)(~(unsigned)(i4 * 4 + q));
                    }
                }
            }
        }
    }
    __syncthreads();

    int acc = 0;
    const int cnt     = sh_cnt;
    const bool fastOK = (cnt <= CAP);

    if (fastOK) {
        // ---- rank sort fused with box prefetch ----
        unsigned long long my = 0ULL;
        float x1 = 0, y1 = 0, x2 = 0, y2 = 0;
        if (tid < cnt) {
            my = keys[tid];
            unsigned idx = ~(unsigned)my;
            const float* p = bx + (size_t)idx * 4;
            x1 = p[0]; y1 = p[1]; x2 = p[2]; y2 = p[3];   // overlaps ranking
        }
        int rank = 0;
        if (tid < cnt) {
            #pragma unroll 4
            for (int j = 0; j < cnt; j++)
                rank += (keys[j] > my);            // distinct keys -> permutation
        }
        __syncthreads();
        if (tid < cnt) {
            keys[rank] = my;
            cx1[rank] = x1; cy1[rank] = y1; cx2[rank] = x2; cy2[rank] = y2;
            car[rank] = __fmul_rn(x2 - x1, y2 - y1);
        }
        __syncthreads();

        // ---- warp-0 ballot walk == greedy NMS ----
        if (tid < 32) {
            const int l = tid;
            int a = 0;
            for (int j2 = 0; j2 < cnt && a < NMS_MAXOUT; j2++) {
                float qx1 = cx1[j2], qy1 = cy1[j2];
                float qx2 = cx2[j2], qy2 = cy2[j2], qa = car[j2];
                bool rej = false;
                if (l < a)
                    rej = iou_reject(ax1[l], ay1[l], ax2[l], ay2[l], aar[l],
                                     qx1, qy1, qx2, qy2, qa);
                if (l + 32 < a)
                    rej |= iou_reject(ax1[l+32], ay1[l+32], ax2[l+32],
                                      ay2[l+32], aar[l+32],
                                      qx1, qy1, qx2, qy2, qa);
                if (__ballot_sync(0xffffffffu, rej) == 0u) {
                    if (l == 0) {
                        unsigned idx = ~(unsigned)keys[j2];
                        orow[a * 3 + 0] = (float)b;
                        orow[a * 3 + 1] = (float)c;
                        orow[a * 3 + 2] = (float)idx;
                        ax1[a] = qx1; ay1[a] = qy1;
                        ax2[a] = qx2; ay2[a] = qy2; aar[a] = qa;
                    }
                    __syncwarp();
                    a++;
                }
            }
            if (l == 0) sh_acc = a;
        }
        __syncthreads();
        acc = sh_acc;
    }

    // ---- exact fallback (block-uniform; statistically never taken) ----
    if (acc < NMS_MAXOUT) {
        for (int i = tid; i < NBUCKET; i += NT) hist[i] = 0;
        __syncthreads();
        for (int i = tid; i < NMS_N; i += NT) {
            float v = sc[i];
            if (v > SCORE_THR)
                atomicAdd(&hist[score_bucket(__float_as_uint(v))], 1u);
        }
        __syncthreads();

        int hi = fastOK ? T0_BUCKET : NBUCKET;
        while (acc < NMS_MAXOUT && hi > 0) {
            if (tid == 0) {
                unsigned cum = 0;
                int lo = hi;
                while (lo > 0) {
                    unsigned n2 = hist[lo - 1];
                    if (cum + n2 > CAP && cum > 0) break;
                    cum += n2;
                    lo--;
                    if (cum >= TARGET) break;
                }
                sh_lo  = lo;
                sh_cnt = 0;
            }
            __syncthreads();
            const int lo = sh_lo;

            for (int i = tid; i < NMS_N; i += NT) {
                float v = sc[i];
                if (v > SCORE_THR) {
                    unsigned bits = __float_as_uint(v);
                    int bkt = (int)score_bucket(bits);
                    if (bkt >= lo && bkt < hi) {
                        int pos = atomicAdd(&sh_cnt, 1);
                        if (pos < CAP)
                            keys[pos] = ((unsigned long long)bits << 32)
                                      | (unsigned)(~(unsigned)i);
                    }
                }
            }
            __syncthreads();
            const int n = (sh_cnt < CAP) ? sh_cnt : CAP;

            unsigned long long my = 0ULL;
            float x1 = 0, y1 = 0, x2 = 0, y2 = 0;
            if (tid < n) {
                my = keys[tid];
                unsigned idx = ~(unsigned)my;
                const float* p = bx + (size_t)idx * 4;
                x1 = p[0]; y1 = p[1]; x2 = p[2]; y2 = p[3];
            }
            int rank = 0;
            if (tid < n) {
                #pragma unroll 4
                for (int j = 0; j < n; j++)
                    rank += (keys[j] > my);
            }
            __syncthreads();
            if (tid < n) {
                keys[rank] = my;
                cx1[rank] = x1; cy1[rank] = y1; cx2[rank] = x2; cy2[rank] = y2;
                car[rank] = __fmul_rn(x2 - x1, y2 - y1);
            }
            __syncthreads();

            if (tid < 32) {
                const int l = tid;
                int a = acc;
                for (int j2 = 0; j2 < n && a < NMS_MAXOUT; j2++) {
                    float qx1 = cx1[j2], qy1 = cy1[j2];
                    float qx2 = cx2[j2], qy2 = cy2[j2], qa = car[j2];
                    bool rej = false;
                    if (l < a)
                        rej = iou_reject(ax1[l], ay1[l], ax2[l], ay2[l], aar[l],
                                         qx1, qy1, qx2, qy2, qa);
                    if (l + 32 < a)
                        rej |= iou_reject(ax1[l+32], ay1[l+32], ax2[l+32],
                                          ay2[l+32], aar[l+32],
                                          qx1, qy1, qx2, qy2, qa);
                    if (__ballot_sync(0xffffffffu, rej) == 0u) {
                        if (l == 0) {
                            unsigned idx = ~(unsigned)keys[j2];
                            orow[a * 3 + 0] = (float)b;
                            orow[a * 3 + 1] = (float)c;
                            orow[a * 3 + 2] = (float)idx;
                            ax1[a] = qx1; ay1[a] = qy1;
                            ax2[a] = qx2; ay2[a] = qy2; aar[a] = qa;
                        }
                        __syncwarp();
                        a++;
                    }
                }
                if (l == 0) sh_acc = a;
            }
            __syncthreads();
            acc = sh_acc;
            hi  = lo;
        }
    }

    // ---- pad remaining rows with -1 ----
    for (int j = acc * 3 + tid; j < NMS_MAXOUT * 3; j += NT)
        orow[j] = -1.0f;
}

extern "C" void kernel_launch(void* const* d_in, const int* in_sizes, int n_in,
                              void* d_out, int out_size)
{
    const float* boxes  = nullptr;   // 524288 elems
    const float* scores = nullptr;   // 10485760 elems
    for (int i = 0; i < n_in; i++) {
        int sz = in_sizes[i];
        if (sz == NMS_B * NMS_N * 4 || sz == NMS_B * NMS_N * 4 * 4)
            boxes = (const float*)d_in[i];
        else if (sz == NMS_B * NMS_C * NMS_N || sz == NMS_B * NMS_C * NMS_N * 4)
            scores = (const float*)d_in[i];
    }
    if (boxes  == nullptr) boxes  = (const float*)d_in[0];
    if (scores == nullptr) scores = (const float*)d_in[1];

    nms_kernel<<<NMS_B * NMS_C, NT>>>(boxes, scores, (float*)d_out);
}